// round 17
// baseline (speedup 1.0000x reference)
#include <cuda_runtime.h>
#include <math.h>

#define BB 4
#define NN 3000
#define CC 21
#define BN (BB*NN)

#define NGROUPS (BB*(CC-1))       // 80
#define THREADS 512
#define PREP_PER_BLK 256
#define PREP_BLOCKS ((BN + PREP_PER_BLK - 1) / PREP_PER_BLK)   // 48
#define NBLK (NGROUPS + PREP_BLOCKS)                           // 128
#define MAXM  320
#define WMAX  10

// out layout (float32): [rounded BN*4][sigmoid BN][boxes BN*4][probs BN*C][keep BN]

// sbuf overlay (group path):
//   keys u64 [0,4096) | tlbr f4 [4096,9216) | area f [9216,10496) | sidx i32 [10496,11776)
//   keptw u32 [11776,11816)
//   fallback: keys u64 [0,32768)
__shared__ unsigned char sbuf[32768];
__shared__ unsigned int  maskbuf[MAXM * WMAX];
__shared__ int s_count;

// exact reference-sequence softmax score for class `cls` given 21 logits.
__device__ __forceinline__ float softmax_score(const float* l, float m, int cls)
{
    float sum = 0.0f;
    #pragma unroll
    for (int c = 0; c < CC; c++) sum += expf(l[c] - m);
    float inv = __fdiv_rn(1.0f, sum);
    return __fmul_rn(expf(l[cls] - m), inv);
}

__device__ __forceinline__ void load_box(const float* __restrict__ nms_reg,
                                         const float* __restrict__ rcnn_reg,
                                         float red, int gidx, float4* box)
{
    float4 r  = ((const float4*)nms_reg)[gidx];
    float4 rg = ((const float4*)rcnn_reg)[gidx];
    float q0 = __fdiv_rn(floorf(__fmul_rn(r.x, red)), red);
    float q1 = __fdiv_rn(floorf(__fmul_rn(r.y, red)), red);
    float q2 = __fdiv_rn(ceilf(__fmul_rn(r.z, red)), red);
    float q3 = __fdiv_rn(ceilf(__fmul_rn(r.w, red)), red);
    box->x = __fadd_rn(rg.x, q0);
    box->y = __fadd_rn(rg.y, q1);
    box->z = __fadd_rn(rg.z, q2);
    box->w = __fadd_rn(rg.w, q3);
}

// bit-exact replica of (__fdiv_rn(inter, d) > 0.5f) with ~zero MUFU use.
__device__ __forceinline__ bool iou_gt_half(float inter, float d)
{
    float t2 = 2.0f * inter;
    if (!(t2 > d)) return false;
    if (t2 < __fmul_rn(d, 1.000001f))
        return __fdiv_rn(inter, d) > 0.5f;
    return true;
}

__global__ void __launch_bounds__(THREADS)
fused_kernel(const float* __restrict__ nms_reg,
             const float* __restrict__ nms_cls,
             const float* __restrict__ rcnn_reg,
             const float* __restrict__ rcnn_cls,
             const unsigned int* __restrict__ red_raw,
             float* __restrict__ out)
{
    int tid  = threadIdx.x;
    int lane = tid & 31;
    int bid  = blockIdx.x;

    unsigned int wr = red_raw[0];
    float red = (wr < 0x10000u) ? (float)wr : __uint_as_float(wr);

    float* o_keep = out + BN * 9 + BN * CC;

    if (bid >= NGROUPS) {
        // ---------------- prep path (256 boxes/block -> MUFU spread) --------
        if (tid >= PREP_PER_BLK) return;
        int idx = (bid - NGROUPS) * PREP_PER_BLK + tid;
        if (idx >= BN) return;

        float* o_round = out;
        float* o_sig   = out + BN * 4;
        float* o_boxes = out + BN * 5;
        float* o_probs = out + BN * 9;

        float4 r = ((const float4*)nms_reg)[idx];
        float q0 = __fdiv_rn(floorf(__fmul_rn(r.x, red)), red);
        float q1 = __fdiv_rn(floorf(__fmul_rn(r.y, red)), red);
        float q2 = __fdiv_rn(ceilf(__fmul_rn(r.z, red)), red);
        float q3 = __fdiv_rn(ceilf(__fmul_rn(r.w, red)), red);
        ((float4*)o_round)[idx] = make_float4(q0, q1, q2, q3);

        float4 rg = ((const float4*)rcnn_reg)[idx];
        ((float4*)o_boxes)[idx] = make_float4(
            __fadd_rn(rg.x, q0), __fadd_rn(rg.y, q1),
            __fadd_rn(rg.z, q2), __fadd_rn(rg.w, q3));

        float s = nms_cls[idx];
        o_sig[idx] = 1.0f / (1.0f + expf(-s));

        float l[CC];
        float m = -INFINITY;
        #pragma unroll
        for (int c = 0; c < CC; c++) {
            l[c] = rcnn_cls[(size_t)idx * CC + c];
            m = fmaxf(m, l[c]);
        }
        float p[CC];
        float sum = 0.0f;
        #pragma unroll
        for (int c = 0; c < CC; c++) {
            p[c] = expf(l[c] - m);
            sum += p[c];
        }
        float inv = __fdiv_rn(1.0f, sum);
        int   am   = 0;
        float best = -INFINITY;
        #pragma unroll
        for (int c = 0; c < CC; c++) {
            p[c] = __fmul_rn(p[c], inv);
            o_probs[(size_t)idx * CC + c] = p[c];
            if (p[c] > best) { best = p[c]; am = c; }
        }
        if (am == 0) o_keep[idx] = 0.0f;   // amax==0 boxes are never kept
        return;
    }

    // ------------------------- group path -------------------------
    int b   = bid / (CC - 1);
    int cls = 1 + bid % (CC - 1);

    unsigned long long* keys = (unsigned long long*)sbuf;

    if (tid == 0) s_count = 0;
    __syncthreads();

    // gather: cheap tree-max gate inline; exact chain only for ~5% survivors.
    for (int n = tid; n < NN; n += THREADS) {
        const float* lg = rcnn_cls + ((size_t)b * NN + n) * CC;
        float l[CC];
        #pragma unroll
        for (int c = 0; c < CC; c++) l[c] = lg[c];

        // depth-5 fmax tree (independent ops; no long dependent chain)
        float a0  = fmaxf(l[0],  l[1]);
        float a1  = fmaxf(l[2],  l[3]);
        float a2  = fmaxf(l[4],  l[5]);
        float a3  = fmaxf(l[6],  l[7]);
        float a4  = fmaxf(l[8],  l[9]);
        float a5  = fmaxf(l[10], l[11]);
        float a6  = fmaxf(l[12], l[13]);
        float a7  = fmaxf(l[14], l[15]);
        float a8  = fmaxf(l[16], l[17]);
        float a9  = fmaxf(l[18], l[19]);
        a0 = fmaxf(a0, a1);  a2 = fmaxf(a2, a3);
        a4 = fmaxf(a4, a5);  a6 = fmaxf(a6, a7);
        a8 = fmaxf(a8, a9);
        a0 = fmaxf(a0, a2);  a4 = fmaxf(a4, a6);
        a8 = fmaxf(a8, l[20]);
        float mx = fmaxf(fmaxf(a0, a4), a8);

        if (l[cls] >= mx - 1e-5f) {
            // exact reference-sequence test (verbatim R6/R15 body)
            float bestl = -INFINITY, second = -INFINITY;
            int am = 0;
            #pragma unroll
            for (int c = 0; c < CC; c++) {
                float v = l[c];
                if (v > bestl) { second = bestl; bestl = v; am = c; }
                else if (v > second) second = v;
            }
            bool cand;
            float score = 0.0f;
            if (bestl - second > 1e-5f) {
                cand = (am == cls);
                if (cand) score = softmax_score(l, bestl, cls);
            } else {
                float sum = 0.0f;
                float p[CC];
                #pragma unroll
                for (int c = 0; c < CC; c++) { p[c] = expf(l[c] - bestl); sum += p[c]; }
                float inv = __fdiv_rn(1.0f, sum);
                int amp = 0; float bp = -INFINITY;
                #pragma unroll
                for (int c = 0; c < CC; c++) {
                    p[c] = __fmul_rn(p[c], inv);
                    if (p[c] > bp) { bp = p[c]; amp = c; }
                }
                cand = (amp == cls);
                score = p[cls];
            }
            if (cand) {
                int pos = atomicAdd(&s_count, 1);
                if (pos < MAXM) {
                    unsigned int sb = __float_as_uint(score);
                    keys[pos] = ((unsigned long long)sb << 32)
                              | (unsigned long long)(0xFFFFFFFFu - (unsigned)n);
                }
            }
        }
    }
    __syncthreads();
    int M = s_count;
    if (M == 0) return;

    if (M <= MAXM) {
        float4*       tlbr  = (float4*)(sbuf + 4096);
        float*        area  = (float*)(sbuf + 9216);
        int*          sidx  = (int*)(sbuf + 10496);
        unsigned int* keptw = (unsigned int*)(sbuf + 11776);
        const int W = (M + 31) >> 5;

        // rank sort (keys unique -> deterministic descending order)
        unsigned long long myk; int myrank = -1;
        if (tid < M) {
            myk = keys[tid];
            int r = 0;
            for (int j = 0; j < M; j++) r += (keys[j] > myk);
            myrank = r;
        }
        __syncthreads();
        if (myrank >= 0) keys[myrank] = myk;
        __syncthreads();

        // stage sorted boxes (bit-exact recompute) + areas + indices
        if (tid < M) {
            int n = (int)(0xFFFFFFFFu - (unsigned)(keys[tid] & 0xFFFFFFFFu));
            sidx[tid] = n;
            float4 v;
            load_box(nms_reg, rcnn_reg, red, b * NN + n, &v);
            tlbr[tid] = v;
            area[tid] = __fmul_rn(fmaxf(__fsub_rn(v.z, v.x), 0.0f),
                                  fmaxf(__fsub_rn(v.w, v.y), 0.0f));
        }
        __syncthreads();

        // suppression matrix: thread owns (row i, word w); division-free IOU
        int ncells = M * W;
        for (int t = tid; t < ncells; t += THREADS) {
            int i = t / W;
            int w = t - i * W;
            int jbase = w << 5;
            unsigned int word = 0;
            if (jbase + 31 > i) {
                float4 bi = tlbr[i];
                float  ai = area[i];
                #pragma unroll 4
                for (int bit = 0; bit < 32; bit++) {
                    int j = jbase + bit;
                    if (j > i && j < M) {
                        float4 bj = tlbr[j];
                        float ih = fmaxf(__fsub_rn(fminf(bi.z, bj.z), fmaxf(bi.x, bj.x)), 0.0f);
                        float iw = fmaxf(__fsub_rn(fminf(bi.w, bj.w), fmaxf(bi.y, bj.y)), 0.0f);
                        float inter = __fmul_rn(ih, iw);
                        float uni   = __fsub_rn(__fadd_rn(ai, area[j]), inter);
                        float d     = fmaxf(uni, 1e-9f);
                        if (iou_gt_half(inter, d)) word |= (1u << bit);
                    }
                }
            }
            maskbuf[i * W + w] = word;
        }
        __syncthreads();

        // warp 0: branchless chunked greedy scan
        if (tid < 32) {
            unsigned int R = 0u, K = 0u;
            int ldslane = (lane < W) ? lane : (W - 1);
            unsigned int lanemask = (lane < W) ? 0xFFFFFFFFu : 0u;
            for (int c = 0; c < W; c++) {
                unsigned int curw = __shfl_sync(0xFFFFFFFFu, R, c);
                int ibase = c << 5;
                #pragma unroll 8
                for (int bit = 0; bit < 32; bit++) {
                    int i = ibase + bit;
                    unsigned int valid = (i < M) ? 0xFFFFFFFFu : 0u;
                    unsigned int keptm = (~(curw >> bit) & 1u) ? valid : 0u;
                    unsigned int mwc = maskbuf[i * W + c]       & valid;
                    unsigned int mwl = maskbuf[i * W + ldslane] & lanemask & valid;
                    curw |= (mwc & keptm);
                    R    |= (mwl & keptm);
                    K    |= ((lane == c) ? (keptm & (1u << bit)) : 0u);
                }
            }
            if (lane < W) keptw[lane] = K;
        }
        __syncthreads();

        // keep (0/1); in-batch index 0 never kept (reference scan quirk)
        if (tid < M) {
            int n = sidx[tid];
            bool kept = (keptw[tid >> 5] >> (tid & 31)) & 1u;
            o_keep[b * NN + n] = (kept && n != 0) ? 1.0f : 0.0f;
        }
    } else {
        // -------- fallback (M > 320; statistically unreachable) --------
        int P = 1;
        while (P < M) P <<= 1;
        for (int i = M + tid; i < P; i += THREADS) keys[i] = 0ULL;
        __syncthreads();
        for (int k = 2; k <= P; k <<= 1) {
            for (int j = k >> 1; j > 0; j >>= 1) {
                for (int i = tid; i < P; i += THREADS) {
                    int ixj = i ^ j;
                    if (ixj > i) {
                        unsigned long long a = keys[i];
                        unsigned long long c = keys[ixj];
                        bool dirDesc = ((i & k) == 0);
                        if ((a < c) == dirDesc) { keys[i] = c; keys[ixj] = a; }
                    }
                }
                __syncthreads();
            }
        }
        unsigned char* st = (unsigned char*)maskbuf;   // 0=alive 1=supp 2=kept
        for (int i = tid; i < M; i += THREADS) st[i] = 0;
        __syncthreads();
        for (int i = 0; i < M; i++) {
            if (st[i] == 0) {
                int ni = (int)(0xFFFFFFFFu - (unsigned)(keys[i] & 0xFFFFFFFFu));
                float4 vi; load_box(nms_reg, rcnn_reg, red, b * NN + ni, &vi);
                float ai = __fmul_rn(fmaxf(__fsub_rn(vi.z, vi.x), 0.0f),
                                     fmaxf(__fsub_rn(vi.w, vi.y), 0.0f));
                if (tid == 0) st[i] = 2;
                for (int j = i + 1 + tid; j < M; j += THREADS) {
                    if (st[j]) continue;
                    int nj = (int)(0xFFFFFFFFu - (unsigned)(keys[j] & 0xFFFFFFFFu));
                    float4 vj; load_box(nms_reg, rcnn_reg, red, b * NN + nj, &vj);
                    float aj = __fmul_rn(fmaxf(__fsub_rn(vj.z, vj.x), 0.0f),
                                         fmaxf(__fsub_rn(vj.w, vj.y), 0.0f));
                    float ih = fmaxf(__fsub_rn(fminf(vi.z, vj.z), fmaxf(vi.x, vj.x)), 0.0f);
                    float iw = fmaxf(__fsub_rn(fminf(vi.w, vj.w), fmaxf(vi.y, vj.y)), 0.0f);
                    float inter = __fmul_rn(ih, iw);
                    float uni   = __fsub_rn(__fadd_rn(ai, aj), inter);
                    float d     = fmaxf(uni, 1e-9f);
                    if (iou_gt_half(inter, d)) st[j] = 1;
                }
            }
            __syncthreads();
        }
        for (int i = tid; i < M; i += THREADS) {
            int n = (int)(0xFFFFFFFFu - (unsigned)(keys[i] & 0xFFFFFFFFu));
            o_keep[b * NN + n] = (st[i] == 2 && n != 0) ? 1.0f : 0.0f;
        }
    }
}

extern "C" void kernel_launch(void* const* d_in, const int* in_sizes, int n_in,
                              void* d_out, int out_size)
{
    const float* nms_reg  = (const float*)d_in[0];
    const float* nms_cls  = (const float*)d_in[1];
    const float* rcnn_reg = (const float*)d_in[2];
    const float* rcnn_cls = (const float*)d_in[3];
    const unsigned int* red = (const unsigned int*)d_in[4];
    float* out = (float*)d_out;

    fused_kernel<<<NBLK, THREADS>>>(nms_reg, nms_cls, rcnn_reg, rcnn_cls, red, out);
}